// round 12
// baseline (speedup 1.0000x reference)
#include <cuda_runtime.h>
#include <cuda_bf16.h>
#include <math.h>

#define NN 50000
#define NE 800000
#define NT 850000     // NE + NN self loops
#define NGRAPH 512
#define NCLS 120

#define MT1 391                  // ceil(NN/128)
#define GB1 (MT1 * 2)            // gemm1 tiles: 2 col-blocks of 128
#define CNTB 3125                // ceil(NE/256)
#define NODB 196                 // ceil(NN/256)
#define GRID_A (GB1 + NODB)      // hist on side stream

#define SCAN_B   200
#define SCAN_SEG 250             // 200*250 == NN exactly

#define XSLD 68                  // A-tile stride

// ---------------- device scratch (no allocations allowed) ----------------
__device__ __align__(16) __nv_bfloat16 g_h1b[(size_t)NN * 256]; // layer1 feats (bf16)
__device__ __align__(16) __nv_bfloat16 g_h2b[(size_t)NN * 64];  // layer2 feats (bf16)
__device__ __align__(16) __nv_bfloat16 g_x2b[(size_t)NN * 256]; // elu(layer1 out), bf16
__device__ __align__(16) float g_als[NN * 4];
__device__ __align__(16) float g_ald[NN * 4];
__device__ __align__(16) float g_w1[(size_t)NT * 4];   // layer1 edge weights (CSR order)
__device__ int   g_deg[NN];          // invariant: all-zero at entry (reset by scatterS)
__device__ int   g_starts[NN + 1];
__device__ int   g_rank[NE];         // per-edge rank within its dst segment
__device__ int   g_srcs[NT];
__device__ int   g_dst[NT];          // dst node per CSR slot (for scatterW)
__device__ float g_pool[NGRAPH * 64];  // invariant: zero at entry (reset by cls)
__device__ float g_cnt[NGRAPH];        // invariant: zero at entry (reset by cls)

// ---------------- packed f32x2 helpers ----------------
#define FMA2(d, a, b) asm("fma.rn.f32x2 %0, %1, %2, %0;" : "+l"(d) : "l"(a), "l"(b))
#define PACK2(d, x)   asm("mov.b64 %0, {%1, %1};" : "=l"(d) : "f"(x))
#define UNPACK2(lo, hi, d) asm("mov.b64 {%0, %1}, %2;" : "=f"(lo), "=f"(hi) : "l"(d))
#define B2F2(dst, u) { unsigned _lo = (u) << 16, _hi = (u) & 0xffff0000u; \
    asm("mov.b64 %0, {%1, %2};" : "=l"(dst) : "r"(_lo), "r"(_hi)); }

__device__ __forceinline__ float lrelu(float v) { return v > 0.f ? v : 0.2f * v; }

// ---------------- fused GEMM tile (f32x2) + bf16 store + attn-logit epilogue ----------------
// 128-row M tile, NTILE N tile (NG = NTILE/64 column groups of 4 cols/thread).
// B reads are lane-contiguous 16B (2-phase floor); A read as float2 covering (k,k+1).
template<int KDIM, int NTILE, bool ABF16>
__device__ __forceinline__ void gemm_attn_tile(
    const void* __restrict__ Araw, const float* __restrict__ B,
    __nv_bfloat16* __restrict__ Cb, int ldb, int row0, int col0,
    const float* __restrict__ asrc, const float* __restrict__ adst, int hstride)
{
    constexpr int NG = NTILE / 64;     // column groups: 2 (Ka) or 1 (Kb)
    constexpr int NP = NG * 2;         // f32x2 accumulator pairs per thread
    constexpr int BF4 = NTILE / 4;     // float4 per B row
    constexpr int BITERS = 64 * BF4 / 256;
    extern __shared__ float smem_dyn[];
    float* xs = smem_dyn;               // [128][XSLD] (m, k)
    float* ws = smem_dyn + 128 * XSLD;  // [64][NTILE] (k, col)

    int tid = threadIdx.x;             // 256
    int tr = tid >> 4, tc = tid & 15;

    unsigned long long acc[8][NP];
#pragma unroll
    for (int i = 0; i < 8; i++)
#pragma unroll
        for (int p = 0; p < NP; p++) acc[i][p] = 0ull;

    for (int k0 = 0; k0 < KDIM; k0 += 64) {
        if (!ABF16) {
            const float* A = (const float*)Araw;
#pragma unroll
            for (int it = 0; it < 8; it++) {   // A: 128x64 fp32
                int v = it * 256 + tid;
                int r = v >> 4, c4 = v & 15;
                int gr = row0 + r;
                float4 av = (gr < NN) ? *(const float4*)&A[(size_t)gr * KDIM + k0 + c4 * 4]
                                      : make_float4(0.f, 0.f, 0.f, 0.f);
                *(float4*)&xs[r * XSLD + c4 * 4] = av;
            }
        } else {
            const __nv_bfloat16* A = (const __nv_bfloat16*)Araw;
#pragma unroll
            for (int it = 0; it < 4; it++) {   // A: 128x64 bf16 -> fp32
                int v = it * 256 + tid;
                int r = v >> 3, c8 = v & 7;
                int gr = row0 + r;
                uint4 raw = (gr < NN) ? *(const uint4*)&A[(size_t)gr * KDIM + k0 + c8 * 8]
                                      : make_uint4(0u, 0u, 0u, 0u);
                float2 f0 = __bfloat1622float2(*(__nv_bfloat162*)&raw.x);
                float2 f1 = __bfloat1622float2(*(__nv_bfloat162*)&raw.y);
                float2 f2 = __bfloat1622float2(*(__nv_bfloat162*)&raw.z);
                float2 f3 = __bfloat1622float2(*(__nv_bfloat162*)&raw.w);
                *(float4*)&xs[r * XSLD + c8 * 8]     = make_float4(f0.x, f0.y, f1.x, f1.y);
                *(float4*)&xs[r * XSLD + c8 * 8 + 4] = make_float4(f2.x, f2.y, f3.x, f3.y);
            }
        }
#pragma unroll
        for (int it = 0; it < BITERS; it++) {  // B: 64xNTILE fp32
            int v = it * 256 + tid;
            int r = v / BF4, c4 = v % BF4;
            *(float4*)&ws[r * NTILE + c4 * 4] =
                *(const float4*)&B[(size_t)(k0 + r) * ldb + col0 + c4 * 4];
        }
        __syncthreads();
#pragma unroll 2
        for (int k = 0; k < 64; k += 2) {
            float2 a2[8];
#pragma unroll
            for (int i = 0; i < 8; i++)
                a2[i] = *(const float2*)&xs[(tr + 16 * i) * XSLD + k];
#pragma unroll
            for (int kk = 0; kk < 2; kk++) {
                unsigned long long bb[NP];
#pragma unroll
                for (int g = 0; g < NG; g++) {
                    ulonglong2 bv = *(const ulonglong2*)&ws[(k + kk) * NTILE + g * 64 + tc * 4];
                    bb[2 * g] = bv.x; bb[2 * g + 1] = bv.y;
                }
#pragma unroll
                for (int i = 0; i < 8; i++) {
                    unsigned long long aa;
                    PACK2(aa, kk ? a2[i].y : a2[i].x);
#pragma unroll
                    for (int p = 0; p < NP; p++) FMA2(acc[i][p], aa, bb[p]);
                }
            }
        }
        __syncthreads();
    }

    // epilogue: bf16 store + attention logits (per 4-col group)
    float asv[NG][4], adv[NG][4];
#pragma unroll
    for (int g = 0; g < NG; g++)
#pragma unroll
        for (int j = 0; j < 4; j++) {
            asv[g][j] = asrc[col0 + g * 64 + tc * 4 + j];
            adv[g][j] = adst[col0 + g * 64 + tc * 4 + j];
        }
#pragma unroll
    for (int i = 0; i < 8; i++) {
        int gr = row0 + tr + 16 * i;
        float fv[NP * 2];
#pragma unroll
        for (int p = 0; p < NP; p++) UNPACK2(fv[2 * p], fv[2 * p + 1], acc[i][p]);
        if (gr < NN) {
#pragma unroll
            for (int g = 0; g < NG; g++) {
                __nv_bfloat162 p0 = __floats2bfloat162_rn(fv[4 * g], fv[4 * g + 1]);
                __nv_bfloat162 p1 = __floats2bfloat162_rn(fv[4 * g + 2], fv[4 * g + 3]);
                uint2 st = make_uint2(*(unsigned*)&p0, *(unsigned*)&p1);
                *(uint2*)&Cb[(size_t)gr * ldb + col0 + g * 64 + tc * 4] = st;
            }
        }
#pragma unroll
        for (int g = 0; g < NG; g++) {
            float ss = 0.f, sd = 0.f;
#pragma unroll
            for (int j = 0; j < 4; j++) {
                ss += fv[4 * g + j] * asv[g][j];
                sd += fv[4 * g + j] * adv[g][j];
            }
#pragma unroll
            for (int o = 1; o < 16; o <<= 1) {     // reduce across 16 tc lanes
                ss += __shfl_xor_sync(0xffffffffu, ss, o);
                sd += __shfl_xor_sync(0xffffffffu, sd, o);
            }
            if (tc == 0 && gr < NN) {
                int head = (col0 >> 6) + g;
                g_als[gr * hstride + head] = ss;
                g_ald[gr * hstride + head] = sd;
            }
        }
    }
}

// ---------------- K_a: gemm1(+attn1 epi) || graph counts ----------------
__global__ void __launch_bounds__(256) Ka_kernel(
    const float* __restrict__ x, const float* __restrict__ W1,
    const float* __restrict__ a_src1, const float* __restrict__ a_dst1,
    const int* __restrict__ batch)
{
    int b = blockIdx.x;
    if (b < GB1) {
        int row0 = (b >> 1) * 128;
        int col0 = (b & 1) * 128;
        gemm_attn_tile<64, 128, false>(x, W1, g_h1b, 256, row0, col0, a_src1, a_dst1, 4);
    } else {
        int i = (b - GB1) * 256 + threadIdx.x;
        if (i < NN) atomicAdd(&g_cnt[batch[i]], 1.0f);
    }
}

__global__ void __launch_bounds__(256) Kb_kernel(
    const float* __restrict__ W2,
    const float* __restrict__ a_src2, const float* __restrict__ a_dst2)
{
    gemm_attn_tile<256, 64, true>(g_x2b, W2, g_h2b, 64, blockIdx.x * 128, 0,
                                  a_src2, a_dst2, 1);
}

// ---------------- side stream: edge histogram + rank ----------------
__global__ void hist_kernel(const int* __restrict__ ei) {
    int i = blockIdx.x * blockDim.x + threadIdx.x;
    if (i < NE) {
        int d = ei[NE + i];
        g_rank[i] = atomicAdd(&g_deg[d], 1);
    }
}

// ---------------- merged scan ----------------
__device__ __forceinline__ int block_incl_scan256(int v) {
    __shared__ int wsum[8];
    int lane = threadIdx.x & 31, wid = threadIdx.x >> 5;
    int x = v;
#pragma unroll
    for (int o = 1; o < 32; o <<= 1) {
        int y = __shfl_up_sync(0xffffffffu, x, o);
        if (lane >= o) x += y;
    }
    if (lane == 31) wsum[wid] = x;
    __syncthreads();
    if (wid == 0 && lane < 8) {
        int w = wsum[lane];
#pragma unroll
        for (int o = 1; o < 8; o <<= 1) {
            int y = __shfl_up_sync(0x000000ffu, w, o);
            if (lane >= o) w += y;
        }
        wsum[lane] = w;
    }
    __syncthreads();
    if (wid > 0) x += wsum[wid - 1];
    return x;
}

__global__ void scan_kernel() {
    __shared__ int red[8];
    __shared__ int s_boff;
    int b = blockIdx.x, t = threadIdx.x, lane = t & 31, wid = t >> 5;
    int lim = b * SCAN_SEG;
    int partial = 0;
    for (int i = t; i < lim; i += 256) partial += g_deg[i];
#pragma unroll
    for (int o = 16; o; o >>= 1) partial += __shfl_xor_sync(0xffffffffu, partial, o);
    if (lane == 0) red[wid] = partial;
    __syncthreads();
    if (t == 0) {
        int s = 0;
#pragma unroll
        for (int k = 0; k < 8; k++) s += red[k];
        s_boff = s + lim;            // + lim self-loops before this segment
    }
    __syncthreads();
    int boff = s_boff;

    int i = lim + t;
    int v = (t < SCAN_SEG) ? g_deg[i] + 1 : 0;
    int inc = block_incl_scan256(v);
    if (t < SCAN_SEG) g_starts[i] = inc - v + boff;
    if (b == SCAN_B - 1 && t == SCAN_SEG - 1) g_starts[NN] = inc + boff;
}

// scatterS: srcs + dst per slot; resets g_deg. No GEMM dependency.
__global__ void scatterS_kernel(const int* __restrict__ ei) {
    int i = blockIdx.x * blockDim.x + threadIdx.x;
    if (i < NN) g_deg[i] = 0;        // reset invariant for next replay
    int s, d, slot;
    if (i < NE) {
        s = ei[i]; d = ei[NE + i];
        slot = g_starts[d] + g_rank[i];
    } else if (i < NT) {
        s = d = i - NE;
        slot = g_starts[d + 1] - 1;
    } else return;
    g_srcs[slot] = s;
    g_dst[slot] = d;
}

// scatterW: layer1 edge weights in CSR order (needs als/ald from Ka)
__global__ void scatterW_kernel() {
    int i = blockIdx.x * blockDim.x + threadIdx.x;
    if (i >= NT) return;
    int s = g_srcs[i];
    int d = g_dst[i];
    float4 as = *(const float4*)&g_als[s * 4];
    float4 ad = *(const float4*)&g_ald[d * 4];
    float4 w;
    w.x = __expf(lrelu(as.x + ad.x));
    w.y = __expf(lrelu(as.y + ad.y));
    w.z = __expf(lrelu(as.z + ad.z));
    w.w = __expf(lrelu(as.w + ad.w));
    *(float4*)&g_w1[(size_t)i * 4] = w;
}

// ---------------- layer 1 aggregation: weights precomputed, FMA2 accumulate ----------------
__global__ void agg1_kernel(const float* __restrict__ b1) {
    int warp = (blockIdx.x * blockDim.x + threadIdx.x) >> 5;
    int lane = threadIdx.x & 31;
    if (warp >= NN) return;
    int e0 = g_starts[warp], e1 = g_starts[warp + 1];

    int hq = lane >> 3;      // lane covers feats [lane*8, lane*8+8) -> head lane>>3

    unsigned long long acc2[4] = {0ull, 0ull, 0ull, 0ull};
    float ssum = 0.f;
#pragma unroll 4
    for (int i = e0; i < e1; i++) {
        int s = g_srcs[i];                       // uniform -> broadcast
        float wq = g_w1[(size_t)i * 4 + hq];     // 4 addrs/warp in one 16B line
        ssum += wq;
        unsigned long long w2; PACK2(w2, wq);
        uint4 hv = *(const uint4*)(g_h1b + (size_t)s * 256 + lane * 8);
        unsigned long long v0, v1, v2, v3;
        B2F2(v0, hv.x); B2F2(v1, hv.y); B2F2(v2, hv.z); B2F2(v3, hv.w);
        FMA2(acc2[0], w2, v0);
        FMA2(acc2[1], w2, v1);
        FMA2(acc2[2], w2, v2);
        FMA2(acc2[3], w2, v3);
    }
    float inv = 1.f / ssum;

    float acc[8];
#pragma unroll
    for (int q = 0; q < 4; q++) UNPACK2(acc[2 * q], acc[2 * q + 1], acc2[q]);

    float4 bva = *(const float4*)&b1[lane * 8];
    float4 bvb = *(const float4*)&b1[lane * 8 + 4];
    float bv[8] = {bva.x, bva.y, bva.z, bva.w, bvb.x, bvb.y, bvb.z, bvb.w};
    unsigned pk[4];
#pragma unroll
    for (int q = 0; q < 4; q++) {
        float v0 = acc[2 * q] * inv + bv[2 * q];
        float v1 = acc[2 * q + 1] * inv + bv[2 * q + 1];
        v0 = v0 > 0.f ? v0 : expm1f(v0);         // ELU
        v1 = v1 > 0.f ? v1 : expm1f(v1);
        __nv_bfloat162 p = __floats2bfloat162_rn(v0, v1);
        pk[q] = *(unsigned*)&p;
    }
    *(uint4*)(g_x2b + (size_t)warp * 256 + lane * 8) =
        make_uint4(pk[0], pk[1], pk[2], pk[3]);
}

// ---------------- layer 2 aggregation + fused global mean pool ----------------
__global__ void agg2_kernel(const float* __restrict__ b2, const int* __restrict__ batch) {
    int warp = (blockIdx.x * blockDim.x + threadIdx.x) >> 5;
    int lane = threadIdx.x & 31;
    if (warp >= NN) return;
    int e0 = g_starts[warp], e1 = g_starts[warp + 1];
    float ad = g_ald[warp];

    float a0 = 0.f, a1 = 0.f, ssum = 0.f;
#pragma unroll 4
    for (int i = e0; i < e1; i++) {
        int s = g_srcs[i];
        float w = __expf(lrelu(g_als[s] + ad));
        ssum += w;
        unsigned hv = *(const unsigned*)(g_h2b + (size_t)s * 64 + lane * 2);
        float fx = __uint_as_float(hv << 16);
        float fy = __uint_as_float(hv & 0xffff0000u);
        a0 += w * fx; a1 += w * fy;
    }
    float inv = 1.f / ssum;
    int g = batch[warp];
    atomicAdd(&g_pool[g * 64 + lane * 2],     a0 * inv + b2[lane * 2]);
    atomicAdd(&g_pool[g * 64 + lane * 2 + 1], a1 * inv + b2[lane * 2 + 1]);
}

// ---------------- classifier (reads then resets pool/cnt) ----------------
__global__ void cls_kernel(const float* __restrict__ Wc,
                           const float* __restrict__ bc,
                           float* __restrict__ out) {
    int g = blockIdx.x;             // 512 blocks, 128 threads
    __shared__ float emb[64];
    float c = fmaxf(g_cnt[g], 1.f);
    if (threadIdx.x < 64) emb[threadIdx.x] = g_pool[g * 64 + threadIdx.x] / c;
    __syncthreads();
    if (threadIdx.x < 64) g_pool[g * 64 + threadIdx.x] = 0.f;   // reset invariant
    if (threadIdx.x == 64) g_cnt[g] = 0.f;
    int cc = threadIdx.x;
    if (cc < NCLS) {
        float s = bc[cc];
#pragma unroll 16
        for (int d = 0; d < 64; d++) s += emb[d] * Wc[d * NCLS + cc];
        out[g * NCLS + cc] = s;
    }
}

// ---------------- launch ----------------
#define SMEM_KA ((128 * XSLD + 64 * 128) * 4)   // 67584
#define SMEM_KB ((128 * XSLD + 64 * 64) * 4)    // 51200

extern "C" void kernel_launch(void* const* d_in, const int* in_sizes, int n_in,
                              void* d_out, int out_size) {
    const float* x      = (const float*)d_in[0];
    const float* W1     = (const float*)d_in[1];
    const float* a_src1 = (const float*)d_in[2];
    const float* a_dst1 = (const float*)d_in[3];
    const float* b1     = (const float*)d_in[4];
    const float* W2     = (const float*)d_in[5];
    const float* a_src2 = (const float*)d_in[6];
    const float* a_dst2 = (const float*)d_in[7];
    const float* b2     = (const float*)d_in[8];
    const float* Wc     = (const float*)d_in[9];
    const float* bc     = (const float*)d_in[10];
    const int* ei       = (const int*)d_in[11];
    const int* batch    = (const int*)d_in[12];
    float* out = (float*)d_out;

    // Lazily created on first (uncaptured) call; reused on the capture call.
    static cudaStream_t s2 = nullptr;
    static cudaEvent_t evFork = nullptr, evJoin = nullptr;
    if (!s2) {
        cudaStreamCreateWithFlags(&s2, cudaStreamNonBlocking);
        cudaEventCreateWithFlags(&evFork, cudaEventDisableTiming);
        cudaEventCreateWithFlags(&evJoin, cudaEventDisableTiming);
    }

    cudaFuncSetAttribute(Ka_kernel, cudaFuncAttributeMaxDynamicSharedMemorySize, SMEM_KA);
    cudaFuncSetAttribute(Kb_kernel, cudaFuncAttributeMaxDynamicSharedMemorySize, SMEM_KB);

    // fork: CSR build on s2 concurrent with Ka GEMM on default stream
    cudaEventRecord(evFork, 0);
    cudaStreamWaitEvent(s2, evFork, 0);
    hist_kernel<<<CNTB, 256, 0, s2>>>(ei);
    scan_kernel<<<SCAN_B, 256, 0, s2>>>();
    scatterS_kernel<<<(NT + 255) / 256, 256, 0, s2>>>(ei);
    cudaEventRecord(evJoin, s2);

    Ka_kernel<<<GRID_A, 256, SMEM_KA>>>(x, W1, a_src1, a_dst1, batch);

    // join: weights need als/ald (Ka) + srcs/dst (s2)
    cudaStreamWaitEvent(0, evJoin, 0);
    scatterW_kernel<<<(NT + 255) / 256, 256>>>();
    agg1_kernel<<<(NN * 32 + 255) / 256, 256>>>(b1);
    Kb_kernel<<<MT1, 256, SMEM_KB>>>(W2, a_src2, a_dst2);
    agg2_kernel<<<(NN * 32 + 255) / 256, 256>>>(b2, batch);
    cls_kernel<<<NGRAPH, 128>>>(Wc, bc, out);
}

// round 13
// speedup vs baseline: 1.0257x; 1.0257x over previous
#include <cuda_runtime.h>
#include <cuda_bf16.h>
#include <math.h>

#define NN 50000
#define NE 800000
#define NT 850000     // NE + NN self loops
#define NGRAPH 512
#define NCLS 120

#define MT1 391                  // ceil(NN/128)
#define GB1 (MT1 * 4)            // gemm1 tiles: 4 col-blocks of 64 (one head each)
#define CNTB 3125                // ceil(NE/256)
#define NODB 196                 // ceil(NN/256)
#define GRID_A (GB1 + NODB)      // hist on side stream

#define SCAN_B   200
#define SCAN_SEG 250             // 200*250 == NN exactly

#define XSLD 68                  // A-tile stride

// ---------------- device scratch (no allocations allowed) ----------------
__device__ __align__(16) __nv_bfloat16 g_h1b[(size_t)NN * 256]; // layer1 feats (bf16)
__device__ __align__(16) __nv_bfloat16 g_h2b[(size_t)NN * 64];  // layer2 feats (bf16)
__device__ __align__(16) __nv_bfloat16 g_x2b[(size_t)NN * 256]; // elu(layer1 out), bf16
__device__ __align__(16) float g_als[NN * 4];
__device__ __align__(16) float g_ald[NN * 4];
__device__ __align__(16) float g_w1[(size_t)NT * 4];   // layer1 edge weights (CSR order)
__device__ int   g_deg[NN];          // invariant: all-zero at entry (reset by scatterS)
__device__ int   g_starts[NN + 1];
__device__ int   g_rank[NE];         // per-edge rank within its dst segment
__device__ int   g_srcs[NT];
__device__ int   g_dst[NT];          // dst node per CSR slot (for scatterW)
__device__ float g_pool[NGRAPH * 64];  // invariant: zero at entry (reset by cls)
__device__ float g_cnt[NGRAPH];        // invariant: zero at entry (reset by cls)

// ---------------- packed f32x2 helpers ----------------
#define FMA2(d, a, b) asm("fma.rn.f32x2 %0, %1, %2, %0;" : "+l"(d) : "l"(a), "l"(b))
#define PACK2(d, x)   asm("mov.b64 %0, {%1, %1};" : "=l"(d) : "f"(x))
#define UNPACK2(lo, hi, d) asm("mov.b64 {%0, %1}, %2;" : "=f"(lo), "=f"(hi) : "l"(d))
#define B2F2(dst, u) { unsigned _lo = (u) << 16, _hi = (u) & 0xffff0000u; \
    asm("mov.b64 %0, {%1, %2};" : "=l"(dst) : "r"(_lo), "r"(_hi)); }

__device__ __forceinline__ float lrelu(float v) { return v > 0.f ? v : 0.2f * v; }

// ---------------- fused GEMM tile (f32x2) + bf16 store + attn-logit epilogue ----------------
// 128-row M tile, 64-col N tile (one head). 256 threads, 8 rows x 4 cols per thread.
// NP=2 acc pairs -> half the registers of the 128-col variant; 3-4 CTAs/SM.
template<int KDIM, bool ABF16>
__device__ __forceinline__ void gemm_attn_tile(
    const void* __restrict__ Araw, const float* __restrict__ B,
    __nv_bfloat16* __restrict__ Cb, int ldb, int row0, int col0,
    const float* __restrict__ asrc, const float* __restrict__ adst, int hstride)
{
    extern __shared__ float smem_dyn[];
    float* xs = smem_dyn;               // [128][XSLD] (m, k)
    float* ws = smem_dyn + 128 * XSLD;  // [64][64] (k, col)

    int tid = threadIdx.x;             // 256
    int tr = tid >> 4, tc = tid & 15;

    unsigned long long acc[8][2];
#pragma unroll
    for (int i = 0; i < 8; i++) { acc[i][0] = 0ull; acc[i][1] = 0ull; }

    for (int k0 = 0; k0 < KDIM; k0 += 64) {
        if (!ABF16) {
            const float* A = (const float*)Araw;
#pragma unroll
            for (int it = 0; it < 8; it++) {   // A: 128x64 fp32
                int v = it * 256 + tid;
                int r = v >> 4, c4 = v & 15;
                int gr = row0 + r;
                float4 av = (gr < NN) ? *(const float4*)&A[(size_t)gr * KDIM + k0 + c4 * 4]
                                      : make_float4(0.f, 0.f, 0.f, 0.f);
                *(float4*)&xs[r * XSLD + c4 * 4] = av;
            }
        } else {
            const __nv_bfloat16* A = (const __nv_bfloat16*)Araw;
#pragma unroll
            for (int it = 0; it < 4; it++) {   // A: 128x64 bf16 -> fp32
                int v = it * 256 + tid;
                int r = v >> 3, c8 = v & 7;
                int gr = row0 + r;
                uint4 raw = (gr < NN) ? *(const uint4*)&A[(size_t)gr * KDIM + k0 + c8 * 8]
                                      : make_uint4(0u, 0u, 0u, 0u);
                float2 f0 = __bfloat1622float2(*(__nv_bfloat162*)&raw.x);
                float2 f1 = __bfloat1622float2(*(__nv_bfloat162*)&raw.y);
                float2 f2 = __bfloat1622float2(*(__nv_bfloat162*)&raw.z);
                float2 f3 = __bfloat1622float2(*(__nv_bfloat162*)&raw.w);
                *(float4*)&xs[r * XSLD + c8 * 8]     = make_float4(f0.x, f0.y, f1.x, f1.y);
                *(float4*)&xs[r * XSLD + c8 * 8 + 4] = make_float4(f2.x, f2.y, f3.x, f3.y);
            }
        }
        {   // B: 64x64 fp32
            int r = tid >> 4, c4 = tid & 15;
#pragma unroll
            for (int it = 0; it < 4; it++)
                *(float4*)&ws[(r + 16 * it) * 64 + c4 * 4] =
                    *(const float4*)&B[(size_t)(k0 + r + 16 * it) * ldb + col0 + c4 * 4];
        }
        __syncthreads();
#pragma unroll 2
        for (int k = 0; k < 64; k += 2) {
            float2 a2[8];
#pragma unroll
            for (int i = 0; i < 8; i++)
                a2[i] = *(const float2*)&xs[(tr + 16 * i) * XSLD + k];
#pragma unroll
            for (int kk = 0; kk < 2; kk++) {
                ulonglong2 bv = *(const ulonglong2*)&ws[(k + kk) * 64 + tc * 4];
#pragma unroll
                for (int i = 0; i < 8; i++) {
                    unsigned long long aa;
                    PACK2(aa, kk ? a2[i].y : a2[i].x);
                    FMA2(acc[i][0], aa, bv.x);
                    FMA2(acc[i][1], aa, bv.y);
                }
            }
        }
        __syncthreads();
    }

    // epilogue: bf16 store + attention logits (this tile = one head)
    float asv[4], adv[4];
#pragma unroll
    for (int j = 0; j < 4; j++) {
        asv[j] = asrc[col0 + tc * 4 + j];
        adv[j] = adst[col0 + tc * 4 + j];
    }
    int head = col0 >> 6;
#pragma unroll
    for (int i = 0; i < 8; i++) {
        int gr = row0 + tr + 16 * i;
        float fv[4];
        UNPACK2(fv[0], fv[1], acc[i][0]);
        UNPACK2(fv[2], fv[3], acc[i][1]);
        if (gr < NN) {
            __nv_bfloat162 p0 = __floats2bfloat162_rn(fv[0], fv[1]);
            __nv_bfloat162 p1 = __floats2bfloat162_rn(fv[2], fv[3]);
            uint2 st = make_uint2(*(unsigned*)&p0, *(unsigned*)&p1);
            *(uint2*)&Cb[(size_t)gr * ldb + col0 + tc * 4] = st;
        }
        float ss = 0.f, sd = 0.f;
#pragma unroll
        for (int j = 0; j < 4; j++) { ss += fv[j] * asv[j]; sd += fv[j] * adv[j]; }
#pragma unroll
        for (int o = 1; o < 16; o <<= 1) {
            ss += __shfl_xor_sync(0xffffffffu, ss, o);
            sd += __shfl_xor_sync(0xffffffffu, sd, o);
        }
        if (tc == 0 && gr < NN) {
            g_als[gr * hstride + head] = ss;
            g_ald[gr * hstride + head] = sd;
        }
    }
}

// ---------------- K_a: gemm1(+attn1 epi) || graph counts ----------------
__global__ void __launch_bounds__(256) Ka_kernel(
    const float* __restrict__ x, const float* __restrict__ W1,
    const float* __restrict__ a_src1, const float* __restrict__ a_dst1,
    const int* __restrict__ batch)
{
    int b = blockIdx.x;
    if (b < GB1) {
        int row0 = (b >> 2) * 128;
        int col0 = (b & 3) * 64;
        gemm_attn_tile<64, false>(x, W1, g_h1b, 256, row0, col0, a_src1, a_dst1, 4);
    } else {
        int i = (b - GB1) * 256 + threadIdx.x;
        if (i < NN) atomicAdd(&g_cnt[batch[i]], 1.0f);
    }
}

__global__ void __launch_bounds__(256) Kb_kernel(
    const float* __restrict__ W2,
    const float* __restrict__ a_src2, const float* __restrict__ a_dst2)
{
    gemm_attn_tile<256, true>(g_x2b, W2, g_h2b, 64, blockIdx.x * 128, 0,
                              a_src2, a_dst2, 1);
}

// ---------------- side stream: edge histogram + rank ----------------
__global__ void hist_kernel(const int* __restrict__ ei) {
    int i = blockIdx.x * blockDim.x + threadIdx.x;
    if (i < NE) {
        int d = ei[NE + i];
        g_rank[i] = atomicAdd(&g_deg[d], 1);
    }
}

// ---------------- merged scan ----------------
__device__ __forceinline__ int block_incl_scan256(int v) {
    __shared__ int wsum[8];
    int lane = threadIdx.x & 31, wid = threadIdx.x >> 5;
    int x = v;
#pragma unroll
    for (int o = 1; o < 32; o <<= 1) {
        int y = __shfl_up_sync(0xffffffffu, x, o);
        if (lane >= o) x += y;
    }
    if (lane == 31) wsum[wid] = x;
    __syncthreads();
    if (wid == 0 && lane < 8) {
        int w = wsum[lane];
#pragma unroll
        for (int o = 1; o < 8; o <<= 1) {
            int y = __shfl_up_sync(0x000000ffu, w, o);
            if (lane >= o) w += y;
        }
        wsum[lane] = w;
    }
    __syncthreads();
    if (wid > 0) x += wsum[wid - 1];
    return x;
}

__global__ void scan_kernel() {
    __shared__ int red[8];
    __shared__ int s_boff;
    int b = blockIdx.x, t = threadIdx.x, lane = t & 31, wid = t >> 5;
    int lim = b * SCAN_SEG;
    int partial = 0;
    for (int i = t; i < lim; i += 256) partial += g_deg[i];
#pragma unroll
    for (int o = 16; o; o >>= 1) partial += __shfl_xor_sync(0xffffffffu, partial, o);
    if (lane == 0) red[wid] = partial;
    __syncthreads();
    if (t == 0) {
        int s = 0;
#pragma unroll
        for (int k = 0; k < 8; k++) s += red[k];
        s_boff = s + lim;            // + lim self-loops before this segment
    }
    __syncthreads();
    int boff = s_boff;

    int i = lim + t;
    int v = (t < SCAN_SEG) ? g_deg[i] + 1 : 0;
    int inc = block_incl_scan256(v);
    if (t < SCAN_SEG) g_starts[i] = inc - v + boff;
    if (b == SCAN_B - 1 && t == SCAN_SEG - 1) g_starts[NN] = inc + boff;
}

// scatterS: srcs + dst per slot; resets g_deg. No GEMM dependency.
__global__ void scatterS_kernel(const int* __restrict__ ei) {
    int i = blockIdx.x * blockDim.x + threadIdx.x;
    if (i < NN) g_deg[i] = 0;        // reset invariant for next replay
    int s, d, slot;
    if (i < NE) {
        s = ei[i]; d = ei[NE + i];
        slot = g_starts[d] + g_rank[i];
    } else if (i < NT) {
        s = d = i - NE;
        slot = g_starts[d + 1] - 1;
    } else return;
    g_srcs[slot] = s;
    g_dst[slot] = d;
}

// scatterW: layer1 edge weights in CSR order (needs als/ald from Ka)
__global__ void scatterW_kernel() {
    int i = blockIdx.x * blockDim.x + threadIdx.x;
    if (i >= NT) return;
    int s = g_srcs[i];
    int d = g_dst[i];
    float4 as = *(const float4*)&g_als[s * 4];
    float4 ad = *(const float4*)&g_ald[d * 4];
    float4 w;
    w.x = __expf(lrelu(as.x + ad.x));
    w.y = __expf(lrelu(as.y + ad.y));
    w.z = __expf(lrelu(as.z + ad.z));
    w.w = __expf(lrelu(as.w + ad.w));
    *(float4*)&g_w1[(size_t)i * 4] = w;
}

// ---------------- layer 1 aggregation: weights precomputed, FMA2 accumulate ----------------
// 64-thread blocks (2 warps): finer granularity -> less degree-imbalance tail.
__global__ void __launch_bounds__(64) agg1_kernel(const float* __restrict__ b1) {
    int warp = (blockIdx.x * blockDim.x + threadIdx.x) >> 5;
    int lane = threadIdx.x & 31;
    if (warp >= NN) return;
    int e0 = g_starts[warp], e1 = g_starts[warp + 1];

    int hq = lane >> 3;      // lane covers feats [lane*8, lane*8+8) -> head lane>>3

    unsigned long long acc2[4] = {0ull, 0ull, 0ull, 0ull};
    float ssum = 0.f;
#pragma unroll 4
    for (int i = e0; i < e1; i++) {
        int s = g_srcs[i];                       // uniform -> broadcast
        float wq = g_w1[(size_t)i * 4 + hq];     // 4 addrs/warp in one 16B line
        ssum += wq;
        unsigned long long w2; PACK2(w2, wq);
        uint4 hv = *(const uint4*)(g_h1b + (size_t)s * 256 + lane * 8);
        unsigned long long v0, v1, v2, v3;
        B2F2(v0, hv.x); B2F2(v1, hv.y); B2F2(v2, hv.z); B2F2(v3, hv.w);
        FMA2(acc2[0], w2, v0);
        FMA2(acc2[1], w2, v1);
        FMA2(acc2[2], w2, v2);
        FMA2(acc2[3], w2, v3);
    }
    float inv = 1.f / ssum;

    float acc[8];
#pragma unroll
    for (int q = 0; q < 4; q++) UNPACK2(acc[2 * q], acc[2 * q + 1], acc2[q]);

    float4 bva = *(const float4*)&b1[lane * 8];
    float4 bvb = *(const float4*)&b1[lane * 8 + 4];
    float bv[8] = {bva.x, bva.y, bva.z, bva.w, bvb.x, bvb.y, bvb.z, bvb.w};
    unsigned pk[4];
#pragma unroll
    for (int q = 0; q < 4; q++) {
        float v0 = acc[2 * q] * inv + bv[2 * q];
        float v1 = acc[2 * q + 1] * inv + bv[2 * q + 1];
        v0 = v0 > 0.f ? v0 : expm1f(v0);         // ELU
        v1 = v1 > 0.f ? v1 : expm1f(v1);
        __nv_bfloat162 p = __floats2bfloat162_rn(v0, v1);
        pk[q] = *(unsigned*)&p;
    }
    *(uint4*)(g_x2b + (size_t)warp * 256 + lane * 8) =
        make_uint4(pk[0], pk[1], pk[2], pk[3]);
}

// ---------------- layer 2 aggregation + fused global mean pool ----------------
__global__ void __launch_bounds__(64) agg2_kernel(const float* __restrict__ b2,
                                                  const int* __restrict__ batch) {
    int warp = (blockIdx.x * blockDim.x + threadIdx.x) >> 5;
    int lane = threadIdx.x & 31;
    if (warp >= NN) return;
    int e0 = g_starts[warp], e1 = g_starts[warp + 1];
    float ad = g_ald[warp];

    float a0 = 0.f, a1 = 0.f, ssum = 0.f;
#pragma unroll 4
    for (int i = e0; i < e1; i++) {
        int s = g_srcs[i];
        float w = __expf(lrelu(g_als[s] + ad));
        ssum += w;
        unsigned hv = *(const unsigned*)(g_h2b + (size_t)s * 64 + lane * 2);
        float fx = __uint_as_float(hv << 16);
        float fy = __uint_as_float(hv & 0xffff0000u);
        a0 += w * fx; a1 += w * fy;
    }
    float inv = 1.f / ssum;
    int g = batch[warp];
    atomicAdd(&g_pool[g * 64 + lane * 2],     a0 * inv + b2[lane * 2]);
    atomicAdd(&g_pool[g * 64 + lane * 2 + 1], a1 * inv + b2[lane * 2 + 1]);
}

// ---------------- classifier (reads then resets pool/cnt) ----------------
__global__ void cls_kernel(const float* __restrict__ Wc,
                           const float* __restrict__ bc,
                           float* __restrict__ out) {
    int g = blockIdx.x;             // 512 blocks, 128 threads
    __shared__ float emb[64];
    float c = fmaxf(g_cnt[g], 1.f);
    if (threadIdx.x < 64) emb[threadIdx.x] = g_pool[g * 64 + threadIdx.x] / c;
    __syncthreads();
    if (threadIdx.x < 64) g_pool[g * 64 + threadIdx.x] = 0.f;   // reset invariant
    if (threadIdx.x == 64) g_cnt[g] = 0.f;
    int cc = threadIdx.x;
    if (cc < NCLS) {
        float s = bc[cc];
#pragma unroll 16
        for (int d = 0; d < 64; d++) s += emb[d] * Wc[d * NCLS + cc];
        out[g * NCLS + cc] = s;
    }
}

// ---------------- launch ----------------
#define SMEM_GEMM ((128 * XSLD + 64 * 64) * 4)   // 51200

extern "C" void kernel_launch(void* const* d_in, const int* in_sizes, int n_in,
                              void* d_out, int out_size) {
    const float* x      = (const float*)d_in[0];
    const float* W1     = (const float*)d_in[1];
    const float* a_src1 = (const float*)d_in[2];
    const float* a_dst1 = (const float*)d_in[3];
    const float* b1     = (const float*)d_in[4];
    const float* W2     = (const float*)d_in[5];
    const float* a_src2 = (const float*)d_in[6];
    const float* a_dst2 = (const float*)d_in[7];
    const float* b2     = (const float*)d_in[8];
    const float* Wc     = (const float*)d_in[9];
    const float* bc     = (const float*)d_in[10];
    const int* ei       = (const int*)d_in[11];
    const int* batch    = (const int*)d_in[12];
    float* out = (float*)d_out;

    // Lazily created on first (uncaptured) call; reused on the capture call.
    static cudaStream_t s2 = nullptr;
    static cudaEvent_t evFork = nullptr, evJoin = nullptr;
    if (!s2) {
        cudaStreamCreateWithFlags(&s2, cudaStreamNonBlocking);
        cudaEventCreateWithFlags(&evFork, cudaEventDisableTiming);
        cudaEventCreateWithFlags(&evJoin, cudaEventDisableTiming);
    }

    cudaFuncSetAttribute(Ka_kernel, cudaFuncAttributeMaxDynamicSharedMemorySize, SMEM_GEMM);
    cudaFuncSetAttribute(Kb_kernel, cudaFuncAttributeMaxDynamicSharedMemorySize, SMEM_GEMM);

    // fork: CSR build on s2 concurrent with Ka GEMM on default stream
    cudaEventRecord(evFork, 0);
    cudaStreamWaitEvent(s2, evFork, 0);
    hist_kernel<<<CNTB, 256, 0, s2>>>(ei);
    scan_kernel<<<SCAN_B, 256, 0, s2>>>();
    scatterS_kernel<<<(NT + 255) / 256, 256, 0, s2>>>(ei);
    cudaEventRecord(evJoin, s2);

    Ka_kernel<<<GRID_A, 256, SMEM_GEMM>>>(x, W1, a_src1, a_dst1, batch);

    // join: weights need als/ald (Ka) + srcs/dst (s2)
    cudaStreamWaitEvent(0, evJoin, 0);
    scatterW_kernel<<<(NT + 255) / 256, 256>>>();
    agg1_kernel<<<(NN * 32 + 63) / 64, 64>>>(b1);
    Kb_kernel<<<MT1, 256, SMEM_GEMM>>>(W2, a_src2, a_dst2);
    agg2_kernel<<<(NN * 32 + 63) / 64, 64>>>(b2, batch);
    cls_kernel<<<NGRAPH, 128>>>(Wc, bc, out);
}

// round 14
// speedup vs baseline: 1.0425x; 1.0164x over previous
#include <cuda_runtime.h>
#include <cuda_bf16.h>
#include <math.h>

#define NN 50000
#define NE 800000
#define NT 850000     // NE + NN self loops
#define NGRAPH 512
#define NCLS 120

#define MT1 391                  // ceil(NN/128)
#define GB1 (MT1 * 2)            // gemm1 tiles: 2 col-blocks of 128
#define CNTB 3125                // ceil(NE/256)
#define NODB 196                 // ceil(NN/256)
#define GRID_A (GB1 + NODB)      // hist on side stream

#define SCAN_B   200
#define SCAN_SEG 250             // 200*250 == NN exactly

#define XSLD 68                  // A-tile stride

// ---------------- device scratch (no allocations allowed) ----------------
__device__ __align__(16) __nv_bfloat16 g_h1b[(size_t)NN * 256]; // layer1 feats (bf16)
__device__ __align__(16) __nv_bfloat16 g_h2b[(size_t)NN * 64];  // layer2 feats (bf16)
__device__ __align__(16) __nv_bfloat16 g_x2b[(size_t)NN * 256]; // elu(layer1 out), bf16
__device__ __align__(16) float g_als[NN * 4];
__device__ __align__(16) float g_ald[NN * 4];
__device__ __align__(16) float g_w1[(size_t)NT * 4];   // layer1 edge weights (CSR order)
__device__ int   g_deg[NN];          // invariant: all-zero at entry (reset by scatterS)
__device__ int   g_starts[NN + 1];
__device__ int   g_rank[NE];         // per-edge rank within its dst segment
__device__ int   g_srcs[NT];
__device__ int   g_dst[NT];          // dst node per CSR slot (for scatterW)
__device__ float g_pool[NGRAPH * 64];  // invariant: zero at entry (reset by cls)
__device__ float g_cnt[NGRAPH];        // invariant: zero at entry (reset by cls)

// ---------------- packed f32x2 helpers ----------------
#define FMA2(d, a, b) asm("fma.rn.f32x2 %0, %1, %2, %0;" : "+l"(d) : "l"(a), "l"(b))
#define PACK2(d, x)   asm("mov.b64 %0, {%1, %1};" : "=l"(d) : "f"(x))
#define UNPACK2(lo, hi, d) asm("mov.b64 {%0, %1}, %2;" : "=f"(lo), "=f"(hi) : "l"(d))
#define B2F2(dst, u) { unsigned _lo = (u) << 16, _hi = (u) & 0xffff0000u; \
    asm("mov.b64 %0, {%1, %2};" : "=l"(dst) : "r"(_lo), "r"(_hi)); }

__device__ __forceinline__ float lrelu(float v) { return v > 0.f ? v : 0.2f * v; }

// ---------------- fused GEMM tile (f32x2) + bf16 store + attn-logit epilogue ----------------
// Round-12 proven shape: 128-row M tile, NTILE N tile (NG = NTILE/64 col groups of 4/thread).
// B reads lane-contiguous 16B (2-phase floor); A read as float2 covering (k,k+1).
template<int KDIM, int NTILE, bool ABF16>
__device__ __forceinline__ void gemm_attn_tile(
    const void* __restrict__ Araw, const float* __restrict__ B,
    __nv_bfloat16* __restrict__ Cb, int ldb, int row0, int col0,
    const float* __restrict__ asrc, const float* __restrict__ adst, int hstride)
{
    constexpr int NG = NTILE / 64;     // column groups: 2 (Ka) or 1 (Kb)
    constexpr int NP = NG * 2;         // f32x2 accumulator pairs per thread
    constexpr int BF4 = NTILE / 4;     // float4 per B row
    constexpr int BITERS = 64 * BF4 / 256;
    extern __shared__ float smem_dyn[];
    float* xs = smem_dyn;               // [128][XSLD] (m, k)
    float* ws = smem_dyn + 128 * XSLD;  // [64][NTILE] (k, col)

    int tid = threadIdx.x;             // 256
    int tr = tid >> 4, tc = tid & 15;

    unsigned long long acc[8][NP];
#pragma unroll
    for (int i = 0; i < 8; i++)
#pragma unroll
        for (int p = 0; p < NP; p++) acc[i][p] = 0ull;

    for (int k0 = 0; k0 < KDIM; k0 += 64) {
        if (!ABF16) {
            const float* A = (const float*)Araw;
#pragma unroll
            for (int it = 0; it < 8; it++) {   // A: 128x64 fp32
                int v = it * 256 + tid;
                int r = v >> 4, c4 = v & 15;
                int gr = row0 + r;
                float4 av = (gr < NN) ? *(const float4*)&A[(size_t)gr * KDIM + k0 + c4 * 4]
                                      : make_float4(0.f, 0.f, 0.f, 0.f);
                *(float4*)&xs[r * XSLD + c4 * 4] = av;
            }
        } else {
            const __nv_bfloat16* A = (const __nv_bfloat16*)Araw;
#pragma unroll
            for (int it = 0; it < 4; it++) {   // A: 128x64 bf16 -> fp32
                int v = it * 256 + tid;
                int r = v >> 3, c8 = v & 7;
                int gr = row0 + r;
                uint4 raw = (gr < NN) ? *(const uint4*)&A[(size_t)gr * KDIM + k0 + c8 * 8]
                                      : make_uint4(0u, 0u, 0u, 0u);
                float2 f0 = __bfloat1622float2(*(__nv_bfloat162*)&raw.x);
                float2 f1 = __bfloat1622float2(*(__nv_bfloat162*)&raw.y);
                float2 f2 = __bfloat1622float2(*(__nv_bfloat162*)&raw.z);
                float2 f3 = __bfloat1622float2(*(__nv_bfloat162*)&raw.w);
                *(float4*)&xs[r * XSLD + c8 * 8]     = make_float4(f0.x, f0.y, f1.x, f1.y);
                *(float4*)&xs[r * XSLD + c8 * 8 + 4] = make_float4(f2.x, f2.y, f3.x, f3.y);
            }
        }
#pragma unroll
        for (int it = 0; it < BITERS; it++) {  // B: 64xNTILE fp32
            int v = it * 256 + tid;
            int r = v / BF4, c4 = v % BF4;
            *(float4*)&ws[r * NTILE + c4 * 4] =
                *(const float4*)&B[(size_t)(k0 + r) * ldb + col0 + c4 * 4];
        }
        __syncthreads();
#pragma unroll 2
        for (int k = 0; k < 64; k += 2) {
            float2 a2[8];
#pragma unroll
            for (int i = 0; i < 8; i++)
                a2[i] = *(const float2*)&xs[(tr + 16 * i) * XSLD + k];
#pragma unroll
            for (int kk = 0; kk < 2; kk++) {
                unsigned long long bb[NP];
#pragma unroll
                for (int g = 0; g < NG; g++) {
                    ulonglong2 bv = *(const ulonglong2*)&ws[(k + kk) * NTILE + g * 64 + tc * 4];
                    bb[2 * g] = bv.x; bb[2 * g + 1] = bv.y;
                }
#pragma unroll
                for (int i = 0; i < 8; i++) {
                    unsigned long long aa;
                    PACK2(aa, kk ? a2[i].y : a2[i].x);
#pragma unroll
                    for (int p = 0; p < NP; p++) FMA2(acc[i][p], aa, bb[p]);
                }
            }
        }
        __syncthreads();
    }

    // epilogue: bf16 store + attention logits (per 4-col group)
    float asv[NG][4], adv[NG][4];
#pragma unroll
    for (int g = 0; g < NG; g++)
#pragma unroll
        for (int j = 0; j < 4; j++) {
            asv[g][j] = asrc[col0 + g * 64 + tc * 4 + j];
            adv[g][j] = adst[col0 + g * 64 + tc * 4 + j];
        }
#pragma unroll
    for (int i = 0; i < 8; i++) {
        int gr = row0 + tr + 16 * i;
        float fv[NP * 2];
#pragma unroll
        for (int p = 0; p < NP; p++) UNPACK2(fv[2 * p], fv[2 * p + 1], acc[i][p]);
        if (gr < NN) {
#pragma unroll
            for (int g = 0; g < NG; g++) {
                __nv_bfloat162 p0 = __floats2bfloat162_rn(fv[4 * g], fv[4 * g + 1]);
                __nv_bfloat162 p1 = __floats2bfloat162_rn(fv[4 * g + 2], fv[4 * g + 3]);
                uint2 st = make_uint2(*(unsigned*)&p0, *(unsigned*)&p1);
                *(uint2*)&Cb[(size_t)gr * ldb + col0 + g * 64 + tc * 4] = st;
            }
        }
#pragma unroll
        for (int g = 0; g < NG; g++) {
            float ss = 0.f, sd = 0.f;
#pragma unroll
            for (int j = 0; j < 4; j++) {
                ss += fv[4 * g + j] * asv[g][j];
                sd += fv[4 * g + j] * adv[g][j];
            }
#pragma unroll
            for (int o = 1; o < 16; o <<= 1) {     // reduce across 16 tc lanes
                ss += __shfl_xor_sync(0xffffffffu, ss, o);
                sd += __shfl_xor_sync(0xffffffffu, sd, o);
            }
            if (tc == 0 && gr < NN) {
                int head = (col0 >> 6) + g;
                g_als[gr * hstride + head] = ss;
                g_ald[gr * hstride + head] = sd;
            }
        }
    }
}

// ---------------- K_a: gemm1(+attn1 epi) || graph counts ----------------
__global__ void __launch_bounds__(256) Ka_kernel(
    const float* __restrict__ x, const float* __restrict__ W1,
    const float* __restrict__ a_src1, const float* __restrict__ a_dst1,
    const int* __restrict__ batch)
{
    int b = blockIdx.x;
    if (b < GB1) {
        int row0 = (b >> 1) * 128;
        int col0 = (b & 1) * 128;
        gemm_attn_tile<64, 128, false>(x, W1, g_h1b, 256, row0, col0, a_src1, a_dst1, 4);
    } else {
        int i = (b - GB1) * 256 + threadIdx.x;
        if (i < NN) atomicAdd(&g_cnt[batch[i]], 1.0f);
    }
}

__global__ void __launch_bounds__(256) Kb_kernel(
    const float* __restrict__ W2,
    const float* __restrict__ a_src2, const float* __restrict__ a_dst2)
{
    gemm_attn_tile<256, 64, true>(g_x2b, W2, g_h2b, 64, blockIdx.x * 128, 0,
                                  a_src2, a_dst2, 1);
}

// ---------------- side stream: edge histogram + rank ----------------
__global__ void hist_kernel(const int* __restrict__ ei) {
    int i = blockIdx.x * blockDim.x + threadIdx.x;
    if (i < NE) {
        int d = ei[NE + i];
        g_rank[i] = atomicAdd(&g_deg[d], 1);
    }
}

// ---------------- merged scan ----------------
__device__ __forceinline__ int block_incl_scan256(int v) {
    __shared__ int wsum[8];
    int lane = threadIdx.x & 31, wid = threadIdx.x >> 5;
    int x = v;
#pragma unroll
    for (int o = 1; o < 32; o <<= 1) {
        int y = __shfl_up_sync(0xffffffffu, x, o);
        if (lane >= o) x += y;
    }
    if (lane == 31) wsum[wid] = x;
    __syncthreads();
    if (wid == 0 && lane < 8) {
        int w = wsum[lane];
#pragma unroll
        for (int o = 1; o < 8; o <<= 1) {
            int y = __shfl_up_sync(0x000000ffu, w, o);
            if (lane >= o) w += y;
        }
        wsum[lane] = w;
    }
    __syncthreads();
    if (wid > 0) x += wsum[wid - 1];
    return x;
}

__global__ void scan_kernel() {
    __shared__ int red[8];
    __shared__ int s_boff;
    int b = blockIdx.x, t = threadIdx.x, lane = t & 31, wid = t >> 5;
    int lim = b * SCAN_SEG;
    int partial = 0;
    for (int i = t; i < lim; i += 256) partial += g_deg[i];
#pragma unroll
    for (int o = 16; o; o >>= 1) partial += __shfl_xor_sync(0xffffffffu, partial, o);
    if (lane == 0) red[wid] = partial;
    __syncthreads();
    if (t == 0) {
        int s = 0;
#pragma unroll
        for (int k = 0; k < 8; k++) s += red[k];
        s_boff = s + lim;            // + lim self-loops before this segment
    }
    __syncthreads();
    int boff = s_boff;

    int i = lim + t;
    int v = (t < SCAN_SEG) ? g_deg[i] + 1 : 0;
    int inc = block_incl_scan256(v);
    if (t < SCAN_SEG) g_starts[i] = inc - v + boff;
    if (b == SCAN_B - 1 && t == SCAN_SEG - 1) g_starts[NN] = inc + boff;
}

// scatterS: srcs + dst per slot; resets g_deg. No GEMM dependency.
__global__ void scatterS_kernel(const int* __restrict__ ei) {
    int i = blockIdx.x * blockDim.x + threadIdx.x;
    if (i < NN) g_deg[i] = 0;        // reset invariant for next replay
    int s, d, slot;
    if (i < NE) {
        s = ei[i]; d = ei[NE + i];
        slot = g_starts[d] + g_rank[i];
    } else if (i < NT) {
        s = d = i - NE;
        slot = g_starts[d + 1] - 1;
    } else return;
    g_srcs[slot] = s;
    g_dst[slot] = d;
}

// scatterW: layer1 edge weights in CSR order (needs als/ald from Ka)
__global__ void scatterW_kernel() {
    int i = blockIdx.x * blockDim.x + threadIdx.x;
    if (i >= NT) return;
    int s = g_srcs[i];
    int d = g_dst[i];
    float4 as = *(const float4*)&g_als[s * 4];
    float4 ad = *(const float4*)&g_ald[d * 4];
    float4 w;
    w.x = __expf(lrelu(as.x + ad.x));
    w.y = __expf(lrelu(as.y + ad.y));
    w.z = __expf(lrelu(as.z + ad.z));
    w.w = __expf(lrelu(as.w + ad.w));
    *(float4*)&g_w1[(size_t)i * 4] = w;
}

// ---------------- layer 1 aggregation: weights precomputed, FMA2 accumulate ----------------
// 64-thread blocks (2 warps): finer granularity -> less degree-imbalance tail.
__global__ void __launch_bounds__(64) agg1_kernel(const float* __restrict__ b1) {
    int warp = (blockIdx.x * blockDim.x + threadIdx.x) >> 5;
    int lane = threadIdx.x & 31;
    if (warp >= NN) return;
    int e0 = g_starts[warp], e1 = g_starts[warp + 1];

    int hq = lane >> 3;      // lane covers feats [lane*8, lane*8+8) -> head lane>>3

    unsigned long long acc2[4] = {0ull, 0ull, 0ull, 0ull};
    float ssum = 0.f;
#pragma unroll 4
    for (int i = e0; i < e1; i++) {
        int s = g_srcs[i];                       // uniform -> broadcast
        float wq = g_w1[(size_t)i * 4 + hq];     // 4 addrs/warp in one 16B line
        ssum += wq;
        unsigned long long w2; PACK2(w2, wq);
        uint4 hv = *(const uint4*)(g_h1b + (size_t)s * 256 + lane * 8);
        unsigned long long v0, v1, v2, v3;
        B2F2(v0, hv.x); B2F2(v1, hv.y); B2F2(v2, hv.z); B2F2(v3, hv.w);
        FMA2(acc2[0], w2, v0);
        FMA2(acc2[1], w2, v1);
        FMA2(acc2[2], w2, v2);
        FMA2(acc2[3], w2, v3);
    }
    float inv = 1.f / ssum;

    float acc[8];
#pragma unroll
    for (int q = 0; q < 4; q++) UNPACK2(acc[2 * q], acc[2 * q + 1], acc2[q]);

    float4 bva = *(const float4*)&b1[lane * 8];
    float4 bvb = *(const float4*)&b1[lane * 8 + 4];
    float bv[8] = {bva.x, bva.y, bva.z, bva.w, bvb.x, bvb.y, bvb.z, bvb.w};
    unsigned pk[4];
#pragma unroll
    for (int q = 0; q < 4; q++) {
        float v0 = acc[2 * q] * inv + bv[2 * q];
        float v1 = acc[2 * q + 1] * inv + bv[2 * q + 1];
        v0 = v0 > 0.f ? v0 : expm1f(v0);         // ELU
        v1 = v1 > 0.f ? v1 : expm1f(v1);
        __nv_bfloat162 p = __floats2bfloat162_rn(v0, v1);
        pk[q] = *(unsigned*)&p;
    }
    *(uint4*)(g_x2b + (size_t)warp * 256 + lane * 8) =
        make_uint4(pk[0], pk[1], pk[2], pk[3]);
}

// ---------------- layer 2 aggregation + fused global mean pool ----------------
__global__ void __launch_bounds__(64) agg2_kernel(const float* __restrict__ b2,
                                                  const int* __restrict__ batch) {
    int warp = (blockIdx.x * blockDim.x + threadIdx.x) >> 5;
    int lane = threadIdx.x & 31;
    if (warp >= NN) return;
    int e0 = g_starts[warp], e1 = g_starts[warp + 1];
    float ad = g_ald[warp];

    float a0 = 0.f, a1 = 0.f, ssum = 0.f;
#pragma unroll 4
    for (int i = e0; i < e1; i++) {
        int s = g_srcs[i];
        float w = __expf(lrelu(g_als[s] + ad));
        ssum += w;
        unsigned hv = *(const unsigned*)(g_h2b + (size_t)s * 64 + lane * 2);
        float fx = __uint_as_float(hv << 16);
        float fy = __uint_as_float(hv & 0xffff0000u);
        a0 += w * fx; a1 += w * fy;
    }
    float inv = 1.f / ssum;
    int g = batch[warp];
    atomicAdd(&g_pool[g * 64 + lane * 2],     a0 * inv + b2[lane * 2]);
    atomicAdd(&g_pool[g * 64 + lane * 2 + 1], a1 * inv + b2[lane * 2 + 1]);
}

// ---------------- classifier (reads then resets pool/cnt) ----------------
__global__ void cls_kernel(const float* __restrict__ Wc,
                           const float* __restrict__ bc,
                           float* __restrict__ out) {
    int g = blockIdx.x;             // 512 blocks, 128 threads
    __shared__ float emb[64];
    float c = fmaxf(g_cnt[g], 1.f);
    if (threadIdx.x < 64) emb[threadIdx.x] = g_pool[g * 64 + threadIdx.x] / c;
    __syncthreads();
    if (threadIdx.x < 64) g_pool[g * 64 + threadIdx.x] = 0.f;   // reset invariant
    if (threadIdx.x == 64) g_cnt[g] = 0.f;
    int cc = threadIdx.x;
    if (cc < NCLS) {
        float s = bc[cc];
#pragma unroll 16
        for (int d = 0; d < 64; d++) s += emb[d] * Wc[d * NCLS + cc];
        out[g * NCLS + cc] = s;
    }
}

// ---------------- launch ----------------
#define SMEM_KA ((128 * XSLD + 64 * 128) * 4)   // 67584
#define SMEM_KB ((128 * XSLD + 64 * 64) * 4)    // 51200

extern "C" void kernel_launch(void* const* d_in, const int* in_sizes, int n_in,
                              void* d_out, int out_size) {
    const float* x      = (const float*)d_in[0];
    const float* W1     = (const float*)d_in[1];
    const float* a_src1 = (const float*)d_in[2];
    const float* a_dst1 = (const float*)d_in[3];
    const float* b1     = (const float*)d_in[4];
    const float* W2     = (const float*)d_in[5];
    const float* a_src2 = (const float*)d_in[6];
    const float* a_dst2 = (const float*)d_in[7];
    const float* b2     = (const float*)d_in[8];
    const float* Wc     = (const float*)d_in[9];
    const float* bc     = (const float*)d_in[10];
    const int* ei       = (const int*)d_in[11];
    const int* batch    = (const int*)d_in[12];
    float* out = (float*)d_out;

    // Lazily created on first (uncaptured) call; reused on the capture call.
    static cudaStream_t s2 = nullptr;
    static cudaEvent_t evFork = nullptr, evJoin = nullptr;
    if (!s2) {
        cudaStreamCreateWithFlags(&s2, cudaStreamNonBlocking);
        cudaEventCreateWithFlags(&evFork, cudaEventDisableTiming);
        cudaEventCreateWithFlags(&evJoin, cudaEventDisableTiming);
    }

    cudaFuncSetAttribute(Ka_kernel, cudaFuncAttributeMaxDynamicSharedMemorySize, SMEM_KA);
    cudaFuncSetAttribute(Kb_kernel, cudaFuncAttributeMaxDynamicSharedMemorySize, SMEM_KB);

    // fork: CSR build on s2 concurrent with Ka GEMM on default stream
    cudaEventRecord(evFork, 0);
    cudaStreamWaitEvent(s2, evFork, 0);
    hist_kernel<<<CNTB, 256, 0, s2>>>(ei);
    scan_kernel<<<SCAN_B, 256, 0, s2>>>();
    scatterS_kernel<<<(NT + 255) / 256, 256, 0, s2>>>(ei);
    cudaEventRecord(evJoin, s2);

    Ka_kernel<<<GRID_A, 256, SMEM_KA>>>(x, W1, a_src1, a_dst1, batch);

    // join: weights need als/ald (Ka) + srcs/dst (s2)
    cudaStreamWaitEvent(0, evJoin, 0);
    scatterW_kernel<<<(NT + 255) / 256, 256>>>();
    agg1_kernel<<<(NN * 32 + 63) / 64, 64>>>(b1);
    Kb_kernel<<<MT1, 256, SMEM_KB>>>(W2, a_src2, a_dst2);
    agg2_kernel<<<(NN * 32 + 63) / 64, 64>>>(b2, batch);
    cls_kernel<<<NGRAPH, 128>>>(Wc, bc, out);
}